// round 1
// baseline (speedup 1.0000x reference)
#include <cuda_runtime.h>

// Problem shapes (fixed by setup_inputs)
#define S_LEN 2048
#define BATCH 2
#define HID   2048
#define NH    16
#define DH    128
#define N3H   6144           // 3*HID
#define MROWS 4096           // S_LEN*BATCH

// Scratch (static device globals — no dynamic allocation allowed)
__device__ float d_Qg[(size_t)BATCH*NH*S_LEN*DH];
__device__ float d_Kg[(size_t)BATCH*NH*S_LEN*DH];
__device__ float d_Vg[(size_t)BATCH*NH*S_LEN*DH];
__device__ float d_ctx[(size_t)MROWS*HID];

// ---------------------------------------------------------------------------
// SGEMM: 128x128 block tile, BK=8, 256 threads, 8x8 per thread.
// MODE 0: C = A@W + bias, scattered into d_Qg/d_Kg/d_Vg ([b,h,s,d] layout)
// MODE 1: C = d_ctx @ W  (plain row-major write, no bias)
// ---------------------------------------------------------------------------
template<int MODE>
__global__ __launch_bounds__(256) void sgemm_kernel(
    const float* __restrict__ A_in, const float* __restrict__ W,
    const float* __restrict__ bias, float* __restrict__ C,
    int M, int N, int K)
{
    const float* A = (MODE == 1) ? d_ctx : A_in;

    __shared__ float As[8][128];
    __shared__ float Bs[8][128];

    const int tid = threadIdx.x;
    const int tr  = tid >> 4;          // 0..15
    const int tc  = tid & 15;          // 0..15
    const int rowA = blockIdx.y * 128;
    const int colB = blockIdx.x * 128;

    const int la_row = tid >> 1;           // 0..127
    const int la_seg = (tid & 1) * 4;      // 0 or 4
    const int lb_row = tid >> 5;           // 0..7
    const int lb_col = (tid & 31) * 4;     // 0..124

    float acc[8][8];
#pragma unroll
    for (int i = 0; i < 8; i++)
#pragma unroll
        for (int j = 0; j < 8; j++) acc[i][j] = 0.f;

    for (int k0 = 0; k0 < K; k0 += 8) {
        float4 a4 = *(const float4*)(A + (size_t)(rowA + la_row) * K + k0 + la_seg);
        As[la_seg + 0][la_row] = a4.x;
        As[la_seg + 1][la_row] = a4.y;
        As[la_seg + 2][la_row] = a4.z;
        As[la_seg + 3][la_row] = a4.w;
        *(float4*)&Bs[lb_row][lb_col] =
            *(const float4*)(W + (size_t)(k0 + lb_row) * N + colB + lb_col);
        __syncthreads();

#pragma unroll
        for (int k = 0; k < 8; k++) {
            float ra[8], rb[8];
            *(float4*)&ra[0] = *(float4*)&As[k][tr * 8];
            *(float4*)&ra[4] = *(float4*)&As[k][tr * 8 + 4];
            *(float4*)&rb[0] = *(float4*)&Bs[k][tc * 8];
            *(float4*)&rb[4] = *(float4*)&Bs[k][tc * 8 + 4];
#pragma unroll
            for (int i = 0; i < 8; i++)
#pragma unroll
                for (int j = 0; j < 8; j++)
                    acc[i][j] = fmaf(ra[i], rb[j], acc[i][j]);
        }
        __syncthreads();
    }

    if (MODE == 0) {
        // scatter mixed QKV into per-head [b,h,s,d] buffers
#pragma unroll
        for (int i = 0; i < 8; i++) {
            const int row = rowA + tr * 8 + i;   // = s*BATCH + b
            const int s = row >> 1;
            const int b = row & 1;
#pragma unroll
            for (int j = 0; j < 8; j++) {
                const int col = colB + tc * 8 + j;       // 0..6143
                const float v = acc[i][j] + bias[col];
                const int h = col / 384;
                const int r = col - h * 384;
                const int which = r >> 7;                // 0=q,1=k,2=v
                const int dc = r & 127;
                float* dst = (which == 0) ? d_Qg : (which == 1) ? d_Kg : d_Vg;
                dst[(((size_t)(b * NH + h) * S_LEN) + s) * DH + dc] = v;
            }
        }
    } else {
#pragma unroll
        for (int i = 0; i < 8; i++) {
            const int row = rowA + tr * 8 + i;
            float* dst = C + (size_t)row * N + colB + tc * 8;
            *(float4*)&dst[0] = *(float4*)&acc[i][0];
            *(float4*)&dst[4] = *(float4*)&acc[i][4];
        }
    }
}

// ---------------------------------------------------------------------------
// Flash attention, fp32. One block = one (b,h) x 64-row q tile; 256 threads.
// kv tiles of 64, causal tiles beyond the diagonal tile are skipped entirely.
// ---------------------------------------------------------------------------
#define QS_STRIDE 128
#define KS_STRIDE 129
#define VS_STRIDE 132
#define ST_STRIDE 65
#define FLASH_SMEM_FLOATS (64*QS_STRIDE + 64*KS_STRIDE + 64*VS_STRIDE + 64*ST_STRIDE + 3*64)
#define FLASH_SMEM_BYTES  (FLASH_SMEM_FLOATS * 4)

__global__ __launch_bounds__(256) void flash_kernel(const unsigned char* __restrict__ amask)
{
    extern __shared__ float sm[];
    float* qs   = sm;                        // [64][128]
    float* ks   = qs + 64 * QS_STRIDE;       // [64][129]
    float* vs   = ks + 64 * KS_STRIDE;       // [64][132]
    float* st   = vs + 64 * VS_STRIDE;       // [64][65]
    float* mrow = st + 64 * ST_STRIDE;       // [64]
    float* lrow = mrow + 64;                 // [64]
    float* arow = lrow + 64;                 // [64]

    const int tid = threadIdx.x;
    const int ty = tid >> 4;      // 0..15 -> rows ty*4..+3
    const int tx = tid & 15;      // 0..15 -> score cols tx*4..+3 / out cols tx*8..+7
    const int qtile = blockIdx.x;
    const int bh = blockIdx.y;    // b*NH + h
    const int b  = bh >> 4;
    const int h  = bh & 15;
    const int qbase = qtile * 64;

    const float* Qp = d_Qg + (size_t)bh * S_LEN * DH;
    const float* Kp = d_Kg + (size_t)bh * S_LEN * DH;
    const float* Vp = d_Vg + (size_t)bh * S_LEN * DH;
    const unsigned char* mbase = amask + (size_t)b * S_LEN * S_LEN;

    // load Q tile
    for (int i = tid; i < 64 * 32; i += 256) {
        const int r = i >> 5;
        const int c4 = (i & 31) * 4;
        *(float4*)&qs[r * QS_STRIDE + c4] =
            *(const float4*)(Qp + (size_t)(qbase + r) * DH + c4);
    }
    if (tid < 64) { mrow[tid] = -1e30f; lrow[tid] = 0.f; }

    float acc[4][8];
#pragma unroll
    for (int i = 0; i < 4; i++)
#pragma unroll
        for (int j = 0; j < 8; j++) acc[i][j] = 0.f;

    const float invnorm = 0.08838834764831845f; // 1/sqrt(128)

    for (int jt = 0; jt <= qtile; jt++) {
        const int jbase = jt * 64;
        __syncthreads();   // protect ks/vs/st from previous iteration's readers

        // load K,V tiles
        for (int i = tid; i < 64 * 32; i += 256) {
            const int r = i >> 5;
            const int c4 = (i & 31) * 4;
            float4 kv = *(const float4*)(Kp + (size_t)(jbase + r) * DH + c4);
            float* kd = &ks[r * KS_STRIDE + c4];
            kd[0] = kv.x; kd[1] = kv.y; kd[2] = kv.z; kd[3] = kv.w;
            *(float4*)&vs[r * VS_STRIDE + c4] =
                *(const float4*)(Vp + (size_t)(jbase + r) * DH + c4);
        }
        __syncthreads();

        // scores: 4x4 per thread over 64x64 tile
        float sc[4][4];
#pragma unroll
        for (int i = 0; i < 4; i++)
#pragma unroll
            for (int j = 0; j < 4; j++) sc[i][j] = 0.f;

#pragma unroll 4
        for (int k = 0; k < 128; k++) {
            float rq[4], rk[4];
#pragma unroll
            for (int i = 0; i < 4; i++) rq[i] = qs[(ty * 4 + i) * QS_STRIDE + k];
#pragma unroll
            for (int j = 0; j < 4; j++) rk[j] = ks[(tx * 4 + j) * KS_STRIDE + k];
#pragma unroll
            for (int i = 0; i < 4; i++)
#pragma unroll
                for (int j = 0; j < 4; j++)
                    sc[i][j] = fmaf(rq[i], rk[j], sc[i][j]);
        }

        // mask + stage scores in smem
        const bool diag_tile = (jt == qtile);
#pragma unroll
        for (int i = 0; i < 4; i++) {
            const int qi = qbase + ty * 4 + i;
            const unsigned char* mr = mbase + (size_t)qi * S_LEN + jbase;
#pragma unroll
            for (int j = 0; j < 4; j++) {
                const int cj = tx * 4 + j;
                float v = sc[i][j] * invnorm;
                const bool causal = diag_tile && ((jbase + cj) > qi);
                if (causal || mr[cj]) v = -10000.0f;   // TE MASK_FILL
                st[(ty * 4 + i) * ST_STRIDE + cj] = v;
            }
        }
        __syncthreads();

        // online softmax: 4 threads per row
        {
            const int row = tid >> 2;
            const int quad = tid & 3;
            const int cb = quad * 16;
            float mloc = -1e30f;
#pragma unroll
            for (int c = 0; c < 16; c++)
                mloc = fmaxf(mloc, st[row * ST_STRIDE + cb + c]);
            mloc = fmaxf(mloc, __shfl_xor_sync(0xffffffffu, mloc, 1));
            mloc = fmaxf(mloc, __shfl_xor_sync(0xffffffffu, mloc, 2));
            const float mold = mrow[row];
            const float mnew = fmaxf(mold, mloc);
            float ssum = 0.f;
#pragma unroll
            for (int c = 0; c < 16; c++) {
                const float p = expf(st[row * ST_STRIDE + cb + c] - mnew);
                st[row * ST_STRIDE + cb + c] = p;
                ssum += p;
            }
            ssum += __shfl_xor_sync(0xffffffffu, ssum, 1);
            ssum += __shfl_xor_sync(0xffffffffu, ssum, 2);
            if (quad == 0) {
                const float al = expf(mold - mnew);
                arow[row] = al;
                lrow[row] = lrow[row] * al + ssum;
                mrow[row] = mnew;
            }
        }
        __syncthreads();

        // rescale + P@V  (4x8 per thread over 64x128)
#pragma unroll
        for (int i = 0; i < 4; i++) {
            const float al = arow[ty * 4 + i];
#pragma unroll
            for (int j = 0; j < 8; j++) acc[i][j] *= al;
        }
#pragma unroll 2
        for (int c = 0; c < 64; c++) {
            float rv[8];
            *(float4*)&rv[0] = *(float4*)&vs[c * VS_STRIDE + tx * 8];
            *(float4*)&rv[4] = *(float4*)&vs[c * VS_STRIDE + tx * 8 + 4];
#pragma unroll
            for (int i = 0; i < 4; i++) {
                const float p = st[(ty * 4 + i) * ST_STRIDE + c];
#pragma unroll
                for (int j = 0; j < 8; j++)
                    acc[i][j] = fmaf(p, rv[j], acc[i][j]);
            }
        }
    }

    // final normalize + write context in [s,b,H] layout
#pragma unroll
    for (int i = 0; i < 4; i++) {
        const int qi = qbase + ty * 4 + i;
        const float inv = 1.f / lrow[ty * 4 + i];
        float o[8];
#pragma unroll
        for (int j = 0; j < 8; j++) o[j] = acc[i][j] * inv;
        float* dst = d_ctx + ((size_t)qi * BATCH + b) * HID + h * DH + tx * 8;
        *(float4*)&dst[0] = *(float4*)&o[0];
        *(float4*)&dst[4] = *(float4*)&o[4];
    }
}

// ---------------------------------------------------------------------------
extern "C" void kernel_launch(void* const* d_in, const int* in_sizes, int n_in,
                              void* d_out, int out_size)
{
    const float* hs            = (const float*)d_in[0];
    const unsigned char* amask = (const unsigned char*)d_in[1];
    const float* qkv_w         = (const float*)d_in[2];
    const float* qkv_b         = (const float*)d_in[3];
    const float* proj_w        = (const float*)d_in[4];
    const float* proj_b        = (const float*)d_in[5];
    float* out = (float*)d_out;

    (void)in_sizes; (void)n_in;

    // 1. QKV GEMM + bias, scattered into per-head Q/K/V
    dim3 g1(N3H / 128, MROWS / 128);
    sgemm_kernel<0><<<g1, 256>>>(hs, qkv_w, qkv_b, nullptr, MROWS, N3H, HID);

    // 2. fused causal attention
    cudaFuncSetAttribute(flash_kernel,
                         cudaFuncAttributeMaxDynamicSharedMemorySize,
                         FLASH_SMEM_BYTES);
    dim3 g2(S_LEN / 64, BATCH * NH);
    flash_kernel<<<g2, 256, FLASH_SMEM_BYTES>>>(amask);

    // 3. output projection (no bias — reference returns bias separately)
    dim3 g3(HID / 128, MROWS / 128);
    sgemm_kernel<1><<<g3, 256>>>(nullptr, proj_w, nullptr, out, MROWS, HID, HID);

    // 4. the reference returns (out, proj_bias): append bias to output tail
    if (out_size >= MROWS * HID + HID) {
        cudaMemcpyAsync(out + (size_t)MROWS * HID, proj_b,
                        HID * sizeof(float), cudaMemcpyDeviceToDevice);
    }
}

// round 7
// speedup vs baseline: 3.4513x; 3.4513x over previous
#include <cuda_runtime.h>
#include <cstdint>

// Problem shapes (fixed by setup_inputs)
#define S_LEN 2048
#define BATCH 2
#define HID   2048
#define NH    16
#define DH    128
#define N3H   6144           // 3*HID
#define MROWS 4096           // S_LEN*BATCH

// Scratch (static device globals — no dynamic allocation allowed)
__device__ float d_Qg[(size_t)BATCH*NH*S_LEN*DH];
__device__ float d_Kg[(size_t)BATCH*NH*S_LEN*DH];
__device__ float d_Vg[(size_t)BATCH*NH*S_LEN*DH];
__device__ float d_ctx[(size_t)MROWS*HID];
__device__ float d_hsr[(size_t)MROWS*HID];     // tf32-rounded hidden states
__device__ float d_wqr[(size_t)HID*N3H];       // tf32-rounded qkv weight
__device__ float d_wpr[(size_t)HID*HID];       // tf32-rounded proj weight

static __device__ __forceinline__ float tf32r(float x) {
    uint32_t u;
    asm("cvt.rna.tf32.f32 %0, %1;" : "=r"(u) : "f"(x));
    return __uint_as_float(u);
}

static __device__ __forceinline__ void cp16(float* dst, const float* src) {
    uint32_t d = (uint32_t)__cvta_generic_to_shared(dst);
    asm volatile("cp.async.ca.shared.global [%0], [%1], 16;\n" :: "r"(d), "l"(src));
}

static __device__ __forceinline__ void mma_tf32(
    float& d0, float& d1, float& d2, float& d3,
    uint32_t a0, uint32_t a1, uint32_t a2, uint32_t a3,
    uint32_t b0, uint32_t b1)
{
    asm volatile(
        "mma.sync.aligned.m16n8k8.row.col.f32.tf32.tf32.f32 "
        "{%0,%1,%2,%3}, {%4,%5,%6,%7}, {%8,%9}, {%0,%1,%2,%3};"
        : "+f"(d0), "+f"(d1), "+f"(d2), "+f"(d3)
        : "r"(a0), "r"(a1), "r"(a2), "r"(a3), "r"(b0), "r"(b1));
}

// ---------------------------------------------------------------------------
// tf32 round-to-nearest pre-pass
// ---------------------------------------------------------------------------
__global__ void round_tf32_kernel(const float4* __restrict__ in,
                                  float4* __restrict__ out, int n4)
{
    for (int i = blockIdx.x * blockDim.x + threadIdx.x; i < n4;
         i += gridDim.x * blockDim.x) {
        float4 v = in[i];
        v.x = tf32r(v.x); v.y = tf32r(v.y); v.z = tf32r(v.z); v.w = tf32r(v.w);
        out[i] = v;
    }
}

// ---------------------------------------------------------------------------
// tf32 tensor-core GEMM: 128x128 block, BK=32, 256 thr, warp tile 64x32,
// mma.sync.m16n8k8, cp.async double buffer.
// MODE 0: C = A@W + bias scattered (tf32-rounded) into d_Qg/d_Kg/d_Vg
// MODE 1: C = A@W plain row-major (no bias)
// ---------------------------------------------------------------------------
#define BK 32
#define AS_STRIDE 36
#define BS_STRIDE 136
#define ABUF (128 * AS_STRIDE)
#define BBUF (BK * BS_STRIDE)
#define GEMM_SMEM_BYTES ((2 * ABUF + 2 * BBUF) * 4)   // 71680 B

static __device__ __forceinline__ void scatterQKV(int row, int col, float v,
                                                  const float* __restrict__ bias)
{
    const int s = row >> 1, b = row & 1;
    v = tf32r(v + bias[col]);          // pre-round for flash tf32 MMA
    const int h = col / 384;
    const int rr = col - h * 384;
    const int which = rr >> 7;
    const int dc = rr & 127;
    float* dst = (which == 0) ? d_Qg : (which == 1) ? d_Kg : d_Vg;
    dst[(((size_t)(b * NH + h) * S_LEN) + s) * DH + dc] = v;
}

template<int MODE>
__global__ __launch_bounds__(256, 2) void mma_gemm(
    const float* __restrict__ A, const float* __restrict__ W,
    const float* __restrict__ bias, float* __restrict__ C,
    int K, int N)
{
    extern __shared__ float sm[];
    float* As = sm;
    float* Bs = sm + 2 * ABUF;

    const int tid = threadIdx.x;
    const int lane = tid & 31;
    const int w = tid >> 5;
    const int wm = (w >> 2) * 64;
    const int wn = (w & 3) * 32;
    const int qr = lane >> 2;
    const int qc = lane & 3;
    const int rowA = blockIdx.y * 128;
    const int colB = blockIdx.x * 128;

    float acc[4][4][4];
#pragma unroll
    for (int mi = 0; mi < 4; mi++)
#pragma unroll
        for (int ni = 0; ni < 4; ni++)
#pragma unroll
            for (int e = 0; e < 4; e++) acc[mi][ni][e] = 0.f;

    const int nt = K / BK;

    auto load_stage = [&](int s, int k0) {
        float* as = As + s * ABUF;
        float* bs = Bs + s * BBUF;
#pragma unroll
        for (int i = 0; i < 4; i++) {
            const int idx = i * 256 + tid;
            const int r = idx >> 3, c = (idx & 7) * 4;
            cp16(as + r * AS_STRIDE + c, A + (size_t)(rowA + r) * K + k0 + c);
        }
#pragma unroll
        for (int i = 0; i < 4; i++) {
            const int idx = i * 256 + tid;
            const int k = idx >> 5, c = (idx & 31) * 4;
            cp16(bs + k * BS_STRIDE + c, W + (size_t)(k0 + k) * N + colB + c);
        }
        asm volatile("cp.async.commit_group;\n" ::);
    };

    load_stage(0, 0);

    for (int t = 0; t < nt; t++) {
        asm volatile("cp.async.wait_group 0;\n" ::);
        __syncthreads();
        if (t + 1 < nt) load_stage((t + 1) & 1, (t + 1) * BK);

        const float* as = As + (t & 1) * ABUF;
        const float* bs = Bs + (t & 1) * BBUF;

#pragma unroll
        for (int kk = 0; kk < BK; kk += 8) {
            uint32_t af[4][4], bf[4][2];
#pragma unroll
            for (int mi = 0; mi < 4; mi++) {
                const float* ap = as + (wm + mi * 16 + qr) * AS_STRIDE + kk + qc;
                af[mi][0] = __float_as_uint(ap[0]);
                af[mi][1] = __float_as_uint(ap[8 * AS_STRIDE]);
                af[mi][2] = __float_as_uint(ap[4]);
                af[mi][3] = __float_as_uint(ap[8 * AS_STRIDE + 4]);
            }
#pragma unroll
            for (int ni = 0; ni < 4; ni++) {
                const float* bp = bs + (kk + qc) * BS_STRIDE + wn + ni * 8 + qr;
                bf[ni][0] = __float_as_uint(bp[0]);
                bf[ni][1] = __float_as_uint(bp[4 * BS_STRIDE]);
            }
#pragma unroll
            for (int mi = 0; mi < 4; mi++)
#pragma unroll
                for (int ni = 0; ni < 4; ni++)
                    mma_tf32(acc[mi][ni][0], acc[mi][ni][1],
                             acc[mi][ni][2], acc[mi][ni][3],
                             af[mi][0], af[mi][1], af[mi][2], af[mi][3],
                             bf[ni][0], bf[ni][1]);
        }
        __syncthreads();
    }

#pragma unroll
    for (int mi = 0; mi < 4; mi++) {
        const int r0 = rowA + wm + mi * 16 + qr;
        const int r1 = r0 + 8;
#pragma unroll
        for (int ni = 0; ni < 4; ni++) {
            const int c0 = colB + wn + ni * 8 + qc * 2;
            if (MODE == 0) {
                scatterQKV(r0, c0,     acc[mi][ni][0], bias);
                scatterQKV(r0, c0 + 1, acc[mi][ni][1], bias);
                scatterQKV(r1, c0,     acc[mi][ni][2], bias);
                scatterQKV(r1, c0 + 1, acc[mi][ni][3], bias);
            } else {
                *(float2*)&C[(size_t)r0 * N + c0] =
                    make_float2(acc[mi][ni][0], acc[mi][ni][1]);
                *(float2*)&C[(size_t)r1 * N + c0] =
                    make_float2(acc[mi][ni][2], acc[mi][ni][3]);
            }
        }
    }
}

// ---------------------------------------------------------------------------
// Flash attention with tf32 tensor-core MMAs.
// Block = one (b,h) x 64-row q tile, 256 threads (8 warps).
// qtile is REVERSED vs blockIdx.x: longest blocks (most kv iters) launch
// first -> LPT schedule, shorter tail on the last wave.
// ---------------------------------------------------------------------------
#define QS 132   // (4*qr + qc) % 32 distinct -> conflict-free A-frag loads
#define KS 132
#define VS 136   // (8*qc + qr) % 32 distinct -> conflict-free B-frag loads
#define STS 68   // (4*qr + qc) % 32 distinct
#define KBUF (64 * KS)
#define VBUF (64 * VS)
#define FLASH_SMEM_FLOATS (64*QS + 2*KBUF + 2*VBUF + 64*STS + 3*64)
#define FLASH_SMEM_BYTES  (FLASH_SMEM_FLOATS * 4)   // 189184 B

__global__ __launch_bounds__(256) void flash_kernel(const unsigned char* __restrict__ amask)
{
    extern __shared__ float sm[];
    float* qs   = sm;                       // [64][QS]
    float* ks   = qs + 64 * QS;             // [2][64][KS]
    float* vs   = ks + 2 * KBUF;            // [2][64][VS]
    float* st   = vs + 2 * VBUF;            // [64][STS]
    float* mrow = st + 64 * STS;
    float* lrow = mrow + 64;
    float* arow = lrow + 64;

    const int tid  = threadIdx.x;
    const int lane = tid & 31;
    const int w    = tid >> 5;
    const int qr   = lane >> 2;     // 0..7
    const int qc   = lane & 3;      // 0..3
    const int rowg = (w >> 1) * 16; // warp row group
    const int colh = (w & 1);       // score col half / out col half

    const int qtile = (int)gridDim.x - 1 - (int)blockIdx.x;  // longest-first
    const int bh = blockIdx.y;
    const int b  = bh >> 4;
    const int h  = bh & 15;
    const int qbase = qtile * 64;

    const float* Qp = d_Qg + (size_t)bh * S_LEN * DH;
    const float* Kp = d_Kg + (size_t)bh * S_LEN * DH;
    const float* Vp = d_Vg + (size_t)bh * S_LEN * DH;
    const unsigned char* mbase = amask + (size_t)b * S_LEN * S_LEN;

    // load Q tile (plain loads; covered by first loop-top __syncthreads)
#pragma unroll
    for (int i = 0; i < 8; i++) {
        const int idx = i * 256 + tid;
        const int r = idx >> 5, c4 = (idx & 31) * 4;
        *(float4*)&qs[r * QS + c4] =
            *(const float4*)(Qp + (size_t)(qbase + r) * DH + c4);
    }
    if (tid < 64) { mrow[tid] = -1e30f; lrow[tid] = 0.f; }

    auto load_kv = [&](int buf, int jbase) {
        float* kd = ks + buf * KBUF;
        float* vd = vs + buf * VBUF;
        const float* Ksrc = Kp + (size_t)jbase * DH;
        const float* Vsrc = Vp + (size_t)jbase * DH;
#pragma unroll
        for (int i = 0; i < 8; i++) {
            const int idx = i * 256 + tid;
            const int r = idx >> 5, c4 = (idx & 31) * 4;
            cp16(kd + r * KS + c4, Ksrc + (size_t)r * DH + c4);
            cp16(vd + r * VS + c4, Vsrc + (size_t)r * DH + c4);
        }
        asm volatile("cp.async.commit_group;\n" ::);
    };

    load_kv(0, 0);

    float oacc[8][4];
#pragma unroll
    for (int ni = 0; ni < 8; ni++)
#pragma unroll
        for (int e = 0; e < 4; e++) oacc[ni][e] = 0.f;

    const float invnorm = 0.08838834764831845f; // 1/sqrt(128)

    for (int jt = 0; jt <= qtile; jt++) {
        const int jbase = jt * 64;
        asm volatile("cp.async.wait_group 0;\n" ::);
        __syncthreads();
        if (jt < qtile) load_kv((jt + 1) & 1, jbase + 64);

        const float* kb = ks + (jt & 1) * KBUF;
        const float* vb = vs + (jt & 1) * VBUF;

        // ---- scores: 16x32 per warp via MMA ----
        float sc[4][4];
#pragma unroll
        for (int ni = 0; ni < 4; ni++)
#pragma unroll
            for (int e = 0; e < 4; e++) sc[ni][e] = 0.f;

#pragma unroll
        for (int kk = 0; kk < DH; kk += 8) {
            const float* ap = qs + (rowg + qr) * QS + kk + qc;
            uint32_t a0 = __float_as_uint(ap[0]);
            uint32_t a1 = __float_as_uint(ap[8 * QS]);
            uint32_t a2 = __float_as_uint(ap[4]);
            uint32_t a3 = __float_as_uint(ap[8 * QS + 4]);
#pragma unroll
            for (int ni = 0; ni < 4; ni++) {
                const float* bp = kb + (colh * 32 + ni * 8 + qr) * KS + kk + qc;
                mma_tf32(sc[ni][0], sc[ni][1], sc[ni][2], sc[ni][3],
                         a0, a1, a2, a3,
                         __float_as_uint(bp[0]), __float_as_uint(bp[4]));
            }
        }

        // ---- mask + scale, stage to st ----
        const bool diag_tile = (jt == qtile);
        const int qi0 = qbase + rowg + qr;
        const int qi1 = qi0 + 8;
        const unsigned char* mr0 = mbase + (size_t)qi0 * S_LEN + jbase;
        const unsigned char* mr1 = mbase + (size_t)qi1 * S_LEN + jbase;
#pragma unroll
        for (int ni = 0; ni < 4; ni++) {
            const int cj = colh * 32 + ni * 8 + qc * 2;
#pragma unroll
            for (int e = 0; e < 2; e++) {
                const int c = cj + e;
                float v0 = sc[ni][e] * invnorm;
                float v1 = sc[ni][e + 2] * invnorm;
                if ((diag_tile && (jbase + c) > qi0) || mr0[c]) v0 = -10000.0f;
                if ((diag_tile && (jbase + c) > qi1) || mr1[c]) v1 = -10000.0f;
                st[(rowg + qr) * STS + c] = v0;
                st[(rowg + qr + 8) * STS + c] = v1;
            }
        }
        __syncthreads();

        // ---- online softmax: 4 threads per row ----
        {
            const int row = tid >> 2;
            const int quad = tid & 3;
            const int cb = quad * 16;
            float mloc = -1e30f;
#pragma unroll
            for (int c = 0; c < 16; c++)
                mloc = fmaxf(mloc, st[row * STS + cb + c]);
            mloc = fmaxf(mloc, __shfl_xor_sync(0xffffffffu, mloc, 1));
            mloc = fmaxf(mloc, __shfl_xor_sync(0xffffffffu, mloc, 2));
            const float mold = mrow[row];
            const float mnew = fmaxf(mold, mloc);
            float ssum = 0.f;
#pragma unroll
            for (int c = 0; c < 16; c++) {
                const float p = expf(st[row * STS + cb + c] - mnew);
                st[row * STS + cb + c] = tf32r(p);
                ssum += p;
            }
            ssum += __shfl_xor_sync(0xffffffffu, ssum, 1);
            ssum += __shfl_xor_sync(0xffffffffu, ssum, 2);
            if (quad == 0) {
                const float al = expf(mold - mnew);
                arow[row] = al;
                lrow[row] = lrow[row] * al + ssum;
                mrow[row] = mnew;
            }
        }
        __syncthreads();

        // ---- rescale + P@V: 16x64 per warp via MMA ----
        {
            const float al0 = arow[rowg + qr];
            const float al8 = arow[rowg + qr + 8];
#pragma unroll
            for (int ni = 0; ni < 8; ni++) {
                oacc[ni][0] *= al0; oacc[ni][1] *= al0;
                oacc[ni][2] *= al8; oacc[ni][3] *= al8;
            }
        }
#pragma unroll
        for (int kk = 0; kk < 64; kk += 8) {
            const float* ap = st + (rowg + qr) * STS + kk + qc;
            uint32_t a0 = __float_as_uint(ap[0]);
            uint32_t a1 = __float_as_uint(ap[8 * STS]);
            uint32_t a2 = __float_as_uint(ap[4]);
            uint32_t a3 = __float_as_uint(ap[8 * STS + 4]);
#pragma unroll
            for (int ni = 0; ni < 8; ni++) {
                const float* bp = vb + (kk + qc) * VS + colh * 64 + ni * 8 + qr;
                mma_tf32(oacc[ni][0], oacc[ni][1], oacc[ni][2], oacc[ni][3],
                         a0, a1, a2, a3,
                         __float_as_uint(bp[0]), __float_as_uint(bp[4 * VS]));
            }
        }
    }

    // ---- normalize + write ctx [s,b,H] (tf32-rounded for proj GEMM) ----
    {
        const float inv0 = 1.f / lrow[rowg + qr];
        const float inv8 = 1.f / lrow[rowg + qr + 8];
        const int r0 = qbase + rowg + qr;
        const int r1 = r0 + 8;
#pragma unroll
        for (int ni = 0; ni < 8; ni++) {
            const int col = colh * 64 + ni * 8 + qc * 2;
            float* dst0 = d_ctx + ((size_t)r0 * BATCH + b) * HID + h * DH + col;
            float* dst1 = d_ctx + ((size_t)r1 * BATCH + b) * HID + h * DH + col;
            *(float2*)dst0 = make_float2(tf32r(oacc[ni][0] * inv0),
                                         tf32r(oacc[ni][1] * inv0));
            *(float2*)dst1 = make_float2(tf32r(oacc[ni][2] * inv8),
                                         tf32r(oacc[ni][3] * inv8));
        }
    }
}

// ---------------------------------------------------------------------------
extern "C" void kernel_launch(void* const* d_in, const int* in_sizes, int n_in,
                              void* d_out, int out_size)
{
    const float* hs            = (const float*)d_in[0];
    const unsigned char* amask = (const unsigned char*)d_in[1];
    const float* qkv_w         = (const float*)d_in[2];
    const float* qkv_b         = (const float*)d_in[3];
    const float* proj_w        = (const float*)d_in[4];
    const float* proj_b        = (const float*)d_in[5];
    float* out = (float*)d_out;
    (void)in_sizes; (void)n_in;

    float *hsr, *wqr, *wpr, *ctx;
    cudaGetSymbolAddress((void**)&hsr, d_hsr);
    cudaGetSymbolAddress((void**)&wqr, d_wqr);
    cudaGetSymbolAddress((void**)&wpr, d_wpr);
    cudaGetSymbolAddress((void**)&ctx, d_ctx);

    // 0. tf32 round-to-nearest pre-pass on GEMM inputs
    round_tf32_kernel<<<1184, 256>>>((const float4*)hs, (float4*)hsr,
                                     (int)((size_t)MROWS * HID / 4));
    round_tf32_kernel<<<1184, 256>>>((const float4*)qkv_w, (float4*)wqr,
                                     (int)((size_t)HID * N3H / 4));
    round_tf32_kernel<<<1184, 256>>>((const float4*)proj_w, (float4*)wpr,
                                     (int)((size_t)HID * HID / 4));

    // 1. QKV GEMM (tf32 MMA) + bias + tf32-rounded scatter
    cudaFuncSetAttribute(mma_gemm<0>, cudaFuncAttributeMaxDynamicSharedMemorySize,
                         GEMM_SMEM_BYTES);
    dim3 g1(N3H / 128, MROWS / 128);
    mma_gemm<0><<<g1, 256, GEMM_SMEM_BYTES>>>(hsr, wqr, qkv_b, nullptr, HID, N3H);

    // 2. fused causal attention (tf32 MMA, longest-tile-first schedule)
    cudaFuncSetAttribute(flash_kernel, cudaFuncAttributeMaxDynamicSharedMemorySize,
                         FLASH_SMEM_BYTES);
    dim3 g2(S_LEN / 64, BATCH * NH);
    flash_kernel<<<g2, 256, FLASH_SMEM_BYTES>>>(amask);

    // 3. output projection (tf32 MMA)
    cudaFuncSetAttribute(mma_gemm<1>, cudaFuncAttributeMaxDynamicSharedMemorySize,
                         GEMM_SMEM_BYTES);
    dim3 g3(HID / 128, MROWS / 128);
    mma_gemm<1><<<g3, 256, GEMM_SMEM_BYTES>>>(ctx, wpr, nullptr, out, HID, HID);

    // 4. reference returns (out, proj_bias): bias at output tail
    if (out_size >= MROWS * HID + HID) {
        cudaMemcpyAsync(out + (size_t)MROWS * HID, proj_b,
                        HID * sizeof(float), cudaMemcpyDeviceToDevice);
    }
}

// round 17
// speedup vs baseline: 3.6035x; 1.0441x over previous
#include <cuda_runtime.h>
#include <cstdint>

// Problem shapes (fixed by setup_inputs)
#define S_LEN 2048
#define BATCH 2
#define HID   2048
#define NH    16
#define DH    128
#define N3H   6144           // 3*HID
#define MROWS 4096           // S_LEN*BATCH

// Scratch (static device globals — no dynamic allocation allowed)
__device__ float d_Qg[(size_t)BATCH*NH*S_LEN*DH];
__device__ float d_Kg[(size_t)BATCH*NH*S_LEN*DH];
__device__ float d_Vg[(size_t)BATCH*NH*S_LEN*DH];
__device__ float d_ctx[(size_t)MROWS*HID];
__device__ float d_hsr[(size_t)MROWS*HID];     // tf32-rounded hidden states
__device__ float d_wqr[(size_t)HID*N3H];       // tf32-rounded qkv weight
__device__ float d_wpr[(size_t)HID*HID];       // tf32-rounded proj weight

static __device__ __forceinline__ float tf32r(float x) {
    uint32_t u;
    asm("cvt.rna.tf32.f32 %0, %1;" : "=r"(u) : "f"(x));
    return __uint_as_float(u);
}

static __device__ __forceinline__ void cp16(float* dst, const float* src) {
    uint32_t d = (uint32_t)__cvta_generic_to_shared(dst);
    asm volatile("cp.async.ca.shared.global [%0], [%1], 16;\n" :: "r"(d), "l"(src));
}

static __device__ __forceinline__ void mma_tf32(
    float& d0, float& d1, float& d2, float& d3,
    uint32_t a0, uint32_t a1, uint32_t a2, uint32_t a3,
    uint32_t b0, uint32_t b1)
{
    asm volatile(
        "mma.sync.aligned.m16n8k8.row.col.f32.tf32.tf32.f32 "
        "{%0,%1,%2,%3}, {%4,%5,%6,%7}, {%8,%9}, {%0,%1,%2,%3};"
        : "+f"(d0), "+f"(d1), "+f"(d2), "+f"(d3)
        : "r"(a0), "r"(a1), "r"(a2), "r"(a3), "r"(b0), "r"(b1));
}

// ldmatrix x4: 4 tiles of 8 rows x 16B. Lane l supplies address of row (l&7)
// of tile (l>>3). Result: reg j = tile j, lane i holds b32 word (i%4) of row (i/4).
static __device__ __forceinline__ void ldsm_x4(
    uint32_t& r0, uint32_t& r1, uint32_t& r2, uint32_t& r3, uint32_t addr)
{
    asm volatile(
        "ldmatrix.sync.aligned.m8n8.x4.shared.b16 {%0,%1,%2,%3}, [%4];"
        : "=r"(r0), "=r"(r1), "=r"(r2), "=r"(r3) : "r"(addr));
}

// ---------------------------------------------------------------------------
// tf32 round-to-nearest pre-pass
// ---------------------------------------------------------------------------
__global__ void round_tf32_kernel(const float4* __restrict__ in,
                                  float4* __restrict__ out, int n4)
{
    for (int i = blockIdx.x * blockDim.x + threadIdx.x; i < n4;
         i += gridDim.x * blockDim.x) {
        float4 v = in[i];
        v.x = tf32r(v.x); v.y = tf32r(v.y); v.z = tf32r(v.z); v.w = tf32r(v.w);
        out[i] = v;
    }
}

// ---------------------------------------------------------------------------
// tf32 tensor-core GEMM: 128x128 block, BK=32, 256 thr, warp tile 64x32,
// mma.sync.m16n8k8, A-frags via ldmatrix.x4, cp.async double buffer.
// ---------------------------------------------------------------------------
#define BK 32
#define AS_STRIDE 36    // 36%32=4 -> 8-row ldmatrix phases conflict-free
#define BS_STRIDE 136
#define ABUF (128 * AS_STRIDE)
#define BBUF (BK * BS_STRIDE)
#define GEMM_SMEM_BYTES ((2 * ABUF + 2 * BBUF) * 4)   // 71680 B

static __device__ __forceinline__ void scatterQKV2(int row, int col,
                                                   float v0, float v1,
                                                   const float* __restrict__ bias)
{
    const int s = row >> 1, b = row & 1;
    const int h = col / 384;
    const int rr = col - h * 384;
    const int which = rr >> 7;
    const int dc = rr & 127;          // even; dc+1 shares h/which (384,128 even)
    float* dst = (which == 0) ? d_Qg : (which == 1) ? d_Kg : d_Vg;
    *(float2*)&dst[(((size_t)(b * NH + h) * S_LEN) + s) * DH + dc] =
        make_float2(tf32r(v0 + bias[col]), tf32r(v1 + bias[col + 1]));
}

template<int MODE>
__global__ __launch_bounds__(256, 2) void mma_gemm(
    const float* __restrict__ A, const float* __restrict__ W,
    const float* __restrict__ bias, float* __restrict__ C,
    int K, int N)
{
    extern __shared__ float sm[];
    float* As = sm;
    float* Bs = sm + 2 * ABUF;

    const int tid = threadIdx.x;
    const int lane = tid & 31;
    const int w = tid >> 5;
    const int wm = (w >> 2) * 64;
    const int wn = (w & 3) * 32;
    const int qr = lane >> 2;
    const int qc = lane & 3;
    const int lj = lane >> 3, lr = lane & 7;      // ldmatrix lane mapping
    const int rowA = blockIdx.y * 128;
    const int colB = blockIdx.x * 128;

    const uint32_t As_u32 = (uint32_t)__cvta_generic_to_shared(As);

    // per-mi ldmatrix lane byte offsets (tile j: rows +(j&1)*8, cols +(j>>1)*4)
    uint32_t aoff[4];
#pragma unroll
    for (int mi = 0; mi < 4; mi++) {
        const int arow = wm + mi * 16 + ((lj & 1) << 3) + lr;
        aoff[mi] = (uint32_t)((arow * AS_STRIDE + ((lj >> 1) << 2)) * 4);
    }

    float acc[4][4][4];
#pragma unroll
    for (int mi = 0; mi < 4; mi++)
#pragma unroll
        for (int ni = 0; ni < 4; ni++)
#pragma unroll
            for (int e = 0; e < 4; e++) acc[mi][ni][e] = 0.f;

    const int nt = K / BK;

    auto load_stage = [&](int s, int k0) {
        float* as = As + s * ABUF;
        float* bs = Bs + s * BBUF;
#pragma unroll
        for (int i = 0; i < 4; i++) {
            const int idx = i * 256 + tid;
            const int r = idx >> 3, c = (idx & 7) * 4;
            cp16(as + r * AS_STRIDE + c, A + (size_t)(rowA + r) * K + k0 + c);
        }
#pragma unroll
        for (int i = 0; i < 4; i++) {
            const int idx = i * 256 + tid;
            const int k = idx >> 5, c = (idx & 31) * 4;
            cp16(bs + k * BS_STRIDE + c, W + (size_t)(k0 + k) * N + colB + c);
        }
        asm volatile("cp.async.commit_group;\n" ::);
    };

    load_stage(0, 0);

    for (int t = 0; t < nt; t++) {
        asm volatile("cp.async.wait_group 0;\n" ::);
        __syncthreads();
        if (t + 1 < nt) load_stage((t + 1) & 1, (t + 1) * BK);

        const uint32_t abase = As_u32 + (uint32_t)((t & 1) * ABUF * 4);
        const float* bs = Bs + (t & 1) * BBUF;

#pragma unroll
        for (int kk = 0; kk < BK; kk += 8) {
            uint32_t af[4][4], bf[4][2];
#pragma unroll
            for (int mi = 0; mi < 4; mi++)
                ldsm_x4(af[mi][0], af[mi][1], af[mi][2], af[mi][3],
                        abase + aoff[mi] + kk * 4);
#pragma unroll
            for (int ni = 0; ni < 4; ni++) {
                const float* bp = bs + (kk + qc) * BS_STRIDE + wn + ni * 8 + qr;
                bf[ni][0] = __float_as_uint(bp[0]);
                bf[ni][1] = __float_as_uint(bp[4 * BS_STRIDE]);
            }
#pragma unroll
            for (int mi = 0; mi < 4; mi++)
#pragma unroll
                for (int ni = 0; ni < 4; ni++)
                    mma_tf32(acc[mi][ni][0], acc[mi][ni][1],
                             acc[mi][ni][2], acc[mi][ni][3],
                             af[mi][0], af[mi][1], af[mi][2], af[mi][3],
                             bf[ni][0], bf[ni][1]);
        }
        __syncthreads();
    }

#pragma unroll
    for (int mi = 0; mi < 4; mi++) {
        const int r0 = rowA + wm + mi * 16 + qr;
        const int r1 = r0 + 8;
#pragma unroll
        for (int ni = 0; ni < 4; ni++) {
            const int c0 = colB + wn + ni * 8 + qc * 2;
            if (MODE == 0) {
                scatterQKV2(r0, c0, acc[mi][ni][0], acc[mi][ni][1], bias);
                scatterQKV2(r1, c0, acc[mi][ni][2], acc[mi][ni][3], bias);
            } else {
                *(float2*)&C[(size_t)r0 * N + c0] =
                    make_float2(acc[mi][ni][0], acc[mi][ni][1]);
                *(float2*)&C[(size_t)r1 * N + c0] =
                    make_float2(acc[mi][ni][2], acc[mi][ni][3]);
            }
        }
    }
}

// ---------------------------------------------------------------------------
// Flash attention, tf32 MMA, ldmatrix fragment loads, LPT block order.
// ---------------------------------------------------------------------------
#define QS 132
#define KS 132
#define VS 136
#define STS 68
#define KBUF (64 * KS)
#define VBUF (64 * VS)
#define FLASH_SMEM_FLOATS (64*QS + 2*KBUF + 2*VBUF + 64*STS + 3*64)
#define FLASH_SMEM_BYTES  (FLASH_SMEM_FLOATS * 4)   // 189184 B

__global__ __launch_bounds__(256) void flash_kernel(const unsigned char* __restrict__ amask)
{
    extern __shared__ float sm[];
    float* qs   = sm;                       // [64][QS]
    float* ks   = qs + 64 * QS;             // [2][64][KS]
    float* vs   = ks + 2 * KBUF;            // [2][64][VS]
    float* st   = vs + 2 * VBUF;            // [64][STS]
    float* mrow = st + 64 * STS;
    float* lrow = mrow + 64;
    float* arow = lrow + 64;

    const int tid  = threadIdx.x;
    const int lane = tid & 31;
    const int w    = tid >> 5;
    const int qr   = lane >> 2;
    const int qc   = lane & 3;
    const int lj   = lane >> 3, lr = lane & 7;
    const int rowg = (w >> 1) * 16;
    const int colh = (w & 1);

    const int qtile = (int)gridDim.x - 1 - (int)blockIdx.x;  // longest-first
    const int bh = blockIdx.y;
    const int b  = bh >> 4;
    const int h  = bh & 15;
    const int qbase = qtile * 64;

    const float* Qp = d_Qg + (size_t)bh * S_LEN * DH;
    const float* Kp = d_Kg + (size_t)bh * S_LEN * DH;
    const float* Vp = d_Vg + (size_t)bh * S_LEN * DH;
    const unsigned char* mbase = amask + (size_t)b * S_LEN * S_LEN;

    const uint32_t qs_u32 = (uint32_t)__cvta_generic_to_shared(qs);
    const uint32_t ks_u32 = (uint32_t)__cvta_generic_to_shared(ks);
    const uint32_t st_u32 = (uint32_t)__cvta_generic_to_shared(st);

    // ldmatrix lane offsets
    const uint32_t aoff_q =
        (uint32_t)(((rowg + ((lj & 1) << 3) + lr) * QS + ((lj >> 1) << 2)) * 4);
    const uint32_t koff0 =
        (uint32_t)(((colh * 32 + ((lj & 1) << 3) + lr) * KS + ((lj >> 1) << 2)) * 4);
    const uint32_t koff1 = koff0 + (uint32_t)(16 * KS * 4);
    const uint32_t stoff =
        (uint32_t)(((rowg + ((lj & 1) << 3) + lr) * STS + ((lj >> 1) << 2)) * 4);

    // load Q tile
#pragma unroll
    for (int i = 0; i < 8; i++) {
        const int idx = i * 256 + tid;
        const int r = idx >> 5, c4 = (idx & 31) * 4;
        *(float4*)&qs[r * QS + c4] =
            *(const float4*)(Qp + (size_t)(qbase + r) * DH + c4);
    }
    if (tid < 64) { mrow[tid] = -1e30f; lrow[tid] = 0.f; }

    auto load_kv = [&](int buf, int jbase) {
        float* kd = ks + buf * KBUF;
        float* vd = vs + buf * VBUF;
        const float* Ksrc = Kp + (size_t)jbase * DH;
        const float* Vsrc = Vp + (size_t)jbase * DH;
#pragma unroll
        for (int i = 0; i < 8; i++) {
            const int idx = i * 256 + tid;
            const int r = idx >> 5, c4 = (idx & 31) * 4;
            cp16(kd + r * KS + c4, Ksrc + (size_t)r * DH + c4);
            cp16(vd + r * VS + c4, Vsrc + (size_t)r * DH + c4);
        }
        asm volatile("cp.async.commit_group;\n" ::);
    };

    load_kv(0, 0);

    float oacc[8][4];
#pragma unroll
    for (int ni = 0; ni < 8; ni++)
#pragma unroll
        for (int e = 0; e < 4; e++) oacc[ni][e] = 0.f;

    const float invnorm = 0.08838834764831845f; // 1/sqrt(128)

    for (int jt = 0; jt <= qtile; jt++) {
        const int jbase = jt * 64;
        asm volatile("cp.async.wait_group 0;\n" ::);
        __syncthreads();
        if (jt < qtile) load_kv((jt + 1) & 1, jbase + 64);

        const uint32_t kbu = ks_u32 + (uint32_t)((jt & 1) * KBUF * 4);
        const float* vb = vs + (jt & 1) * VBUF;

        // ---- scores: 16x32 per warp via MMA + ldmatrix ----
        float sc[4][4];
#pragma unroll
        for (int ni = 0; ni < 4; ni++)
#pragma unroll
            for (int e = 0; e < 4; e++) sc[ni][e] = 0.f;

#pragma unroll
        for (int kk = 0; kk < DH; kk += 8) {
            uint32_t a0, a1, a2, a3;
            ldsm_x4(a0, a1, a2, a3, qs_u32 + aoff_q + kk * 4);
            // K tiles: r0=b0(ni), r1=b0(ni+1), r2=b1(ni), r3=b1(ni+1)
            uint32_t k00, k01, k02, k03;
            ldsm_x4(k00, k01, k02, k03, kbu + koff0 + kk * 4);
            mma_tf32(sc[0][0], sc[0][1], sc[0][2], sc[0][3],
                     a0, a1, a2, a3, k00, k02);
            mma_tf32(sc[1][0], sc[1][1], sc[1][2], sc[1][3],
                     a0, a1, a2, a3, k01, k03);
            uint32_t k10, k11, k12, k13;
            ldsm_x4(k10, k11, k12, k13, kbu + koff1 + kk * 4);
            mma_tf32(sc[2][0], sc[2][1], sc[2][2], sc[2][3],
                     a0, a1, a2, a3, k10, k12);
            mma_tf32(sc[3][0], sc[3][1], sc[3][2], sc[3][3],
                     a0, a1, a2, a3, k11, k13);
        }

        // ---- mask + scale, stage to st ----
        const bool diag_tile = (jt == qtile);
        const int qi0 = qbase + rowg + qr;
        const int qi1 = qi0 + 8;
        const unsigned char* mr0 = mbase + (size_t)qi0 * S_LEN + jbase;
        const unsigned char* mr1 = mbase + (size_t)qi1 * S_LEN + jbase;
#pragma unroll
        for (int ni = 0; ni < 4; ni++) {
            const int cj = colh * 32 + ni * 8 + qc * 2;
#pragma unroll
            for (int e = 0; e < 2; e++) {
                const int c = cj + e;
                float v0 = sc[ni][e] * invnorm;
                float v1 = sc[ni][e + 2] * invnorm;
                if ((diag_tile && (jbase + c) > qi0) || mr0[c]) v0 = -10000.0f;
                if ((diag_tile && (jbase + c) > qi1) || mr1[c]) v1 = -10000.0f;
                st[(rowg + qr) * STS + c] = v0;
                st[(rowg + qr + 8) * STS + c] = v1;
            }
        }
        __syncthreads();

        // ---- online softmax: 4 threads per row ----
        {
            const int row = tid >> 2;
            const int quad = tid & 3;
            const int cb = quad * 16;
            float mloc = -1e30f;
#pragma unroll
            for (int c = 0; c < 16; c++)
                mloc = fmaxf(mloc, st[row * STS + cb + c]);
            mloc = fmaxf(mloc, __shfl_xor_sync(0xffffffffu, mloc, 1));
            mloc = fmaxf(mloc, __shfl_xor_sync(0xffffffffu, mloc, 2));
            const float mold = mrow[row];
            const float mnew = fmaxf(mold, mloc);
            float ssum = 0.f;
#pragma unroll
            for (int c = 0; c < 16; c++) {
                const float p = __expf(st[row * STS + cb + c] - mnew);
                st[row * STS + cb + c] = tf32r(p);
                ssum += p;
            }
            ssum += __shfl_xor_sync(0xffffffffu, ssum, 1);
            ssum += __shfl_xor_sync(0xffffffffu, ssum, 2);
            if (quad == 0) {
                const float al = __expf(mold - mnew);
                arow[row] = al;
                lrow[row] = lrow[row] * al + ssum;
                mrow[row] = mnew;
            }
        }
        __syncthreads();

        // ---- rescale + P@V: 16x64 per warp ----
        {
            const float al0 = arow[rowg + qr];
            const float al8 = arow[rowg + qr + 8];
#pragma unroll
            for (int ni = 0; ni < 8; ni++) {
                oacc[ni][0] *= al0; oacc[ni][1] *= al0;
                oacc[ni][2] *= al8; oacc[ni][3] *= al8;
            }
        }
#pragma unroll
        for (int kk = 0; kk < 64; kk += 8) {
            uint32_t a0, a1, a2, a3;
            ldsm_x4(a0, a1, a2, a3, st_u32 + stoff + kk * 4);
#pragma unroll
            for (int ni = 0; ni < 8; ni++) {
                const float* bp = vb + (kk + qc) * VS + colh * 64 + ni * 8 + qr;
                mma_tf32(oacc[ni][0], oacc[ni][1], oacc[ni][2], oacc[ni][3],
                         a0, a1, a2, a3,
                         __float_as_uint(bp[0]), __float_as_uint(bp[4 * VS]));
            }
        }
    }

    // ---- normalize + write ctx [s,b,H] (tf32-rounded for proj GEMM) ----
    {
        const float inv0 = 1.f / lrow[rowg + qr];
        const float inv8 = 1.f / lrow[rowg + qr + 8];
        const int r0 = qbase + rowg + qr;
        const int r1 = r0 + 8;
#pragma unroll
        for (int ni = 0; ni < 8; ni++) {
            const int col = colh * 64 + ni * 8 + qc * 2;
            float* dst0 = d_ctx + ((size_t)r0 * BATCH + b) * HID + h * DH + col;
            float* dst1 = d_ctx + ((size_t)r1 * BATCH + b) * HID + h * DH + col;
            *(float2*)dst0 = make_float2(tf32r(oacc[ni][0] * inv0),
                                         tf32r(oacc[ni][1] * inv0));
            *(float2*)dst1 = make_float2(tf32r(oacc[ni][2] * inv8),
                                         tf32r(oacc[ni][3] * inv8));
        }
    }
}

// ---------------------------------------------------------------------------
extern "C" void kernel_launch(void* const* d_in, const int* in_sizes, int n_in,
                              void* d_out, int out_size)
{
    const float* hs            = (const float*)d_in[0];
    const unsigned char* amask = (const unsigned char*)d_in[1];
    const float* qkv_w         = (const float*)d_in[2];
    const float* qkv_b         = (const float*)d_in[3];
    const float* proj_w        = (const float*)d_in[4];
    const float* proj_b        = (const float*)d_in[5];
    float* out = (float*)d_out;
    (void)in_sizes; (void)n_in;

    float *hsr, *wqr, *wpr, *ctx;
    cudaGetSymbolAddress((void**)&hsr, d_hsr);
    cudaGetSymbolAddress((void**)&wqr, d_wqr);
    cudaGetSymbolAddress((void**)&wpr, d_wpr);
    cudaGetSymbolAddress((void**)&ctx, d_ctx);

    // 0. tf32 round-to-nearest pre-pass on GEMM inputs
    round_tf32_kernel<<<1184, 256>>>((const float4*)hs, (float4*)hsr,
                                     (int)((size_t)MROWS * HID / 4));
    round_tf32_kernel<<<1184, 256>>>((const float4*)qkv_w, (float4*)wqr,
                                     (int)((size_t)HID * N3H / 4));
    round_tf32_kernel<<<1184, 256>>>((const float4*)proj_w, (float4*)wpr,
                                     (int)((size_t)HID * HID / 4));

    // 1. QKV GEMM (tf32 MMA + ldmatrix) + bias + tf32-rounded scatter
    cudaFuncSetAttribute(mma_gemm<0>, cudaFuncAttributeMaxDynamicSharedMemorySize,
                         GEMM_SMEM_BYTES);
    dim3 g1(N3H / 128, MROWS / 128);
    mma_gemm<0><<<g1, 256, GEMM_SMEM_BYTES>>>(hsr, wqr, qkv_b, nullptr, HID, N3H);

    // 2. fused causal attention (tf32 MMA, ldmatrix, LPT order)
    cudaFuncSetAttribute(flash_kernel, cudaFuncAttributeMaxDynamicSharedMemorySize,
                         FLASH_SMEM_BYTES);
    dim3 g2(S_LEN / 64, BATCH * NH);
    flash_kernel<<<g2, 256, FLASH_SMEM_BYTES>>>(amask);

    // 3. output projection (tf32 MMA + ldmatrix)
    cudaFuncSetAttribute(mma_gemm<1>, cudaFuncAttributeMaxDynamicSharedMemorySize,
                         GEMM_SMEM_BYTES);
    dim3 g3(HID / 128, MROWS / 128);
    mma_gemm<1><<<g3, 256, GEMM_SMEM_BYTES>>>(ctx, wpr, nullptr, out, HID, HID);

    // 4. reference returns (out, proj_bias): bias at output tail
    if (out_size >= MROWS * HID + HID) {
        cudaMemcpyAsync(out + (size_t)MROWS * HID, proj_b,
                        HID * sizeof(float), cudaMemcpyDeviceToDevice);
    }
}